// round 9
// baseline (speedup 1.0000x reference)
#include <cuda_runtime.h>
#include <cstdint>

// ---------------------------------------------------------------------------
// EdgeGATv2: N=100000 nodes, E=1600000 edges, IN=128, OUT=64 (H=4 x HD=16),
// EDGE_DIM=32.  Output = [rst (N*64 floats) ; alpha (E*4 floats)].
//
// R7: k_edge phase-split (GEMV -> smem -> thread-per-edge epilogue, no
// shuffles, 24 edges/warp, 3 blocks/SM) ; alpha fused into k_pull.
// ---------------------------------------------------------------------------

#define NN    100000
#define NE    1600000
#define OUTD  64
#define NB_SCAN 98          // ceil(NN/1024)

#define EPB   192           // edges per block (k_edge)
#define EPW   24            // edges per warp
#define NBLK_E ((NE + EPB - 1) / EPB)   // 8334

typedef unsigned long long u64;

// ---------------- scratch (no allocations allowed) -------------------------
__device__ float g_fs[(size_t)NN * OUTD];     // 25.6 MB
__device__ float g_fd[(size_t)NN * OUTD];     // 25.6 MB
__device__ float g_logit[(size_t)NE * 4];     // 25.6 MB (reused as ex)
__device__ int   g_maxenc[NN * 4];            // 1.6 MB
__device__ float g_sum[NN * 4];               // 1.6 MB
__device__ int   g_off[NN + 1];               // CSR row offsets
__device__ int   g_cur[NN];                   // degree, then scatter cursor
__device__ int   g_eid[NE];                   // CSR edge ids
__device__ int   g_part[NB_SCAN];             // scan partials
__device__ int   g_partoff[NB_SCAN];

// ---------------- helpers ---------------------------------------------------
__device__ __forceinline__ u64 pack2(float lo, float hi) {
    u64 r; asm("mov.b64 %0, {%1, %2};" : "=l"(r) : "f"(lo), "f"(hi)); return r;
}
__device__ __forceinline__ void fma2(u64& d, u64 a, u64 b) {
    asm("fma.rn.f32x2 %0, %1, %2, %0;" : "+l"(d) : "l"(a), "l"(b));
}
__device__ __forceinline__ float lo32(u64 v) { return __uint_as_float((unsigned)v); }
__device__ __forceinline__ float hi32(u64 v) { return __uint_as_float((unsigned)(v >> 32)); }

__device__ __forceinline__ int fenc(float f) {
    int i = __float_as_int(f);
    return i >= 0 ? i : (i ^ 0x7fffffff);
}
__device__ __forceinline__ float fdec(int e) {
    return __int_as_float(e >= 0 ? e : (e ^ 0x7fffffff));
}

__device__ __forceinline__ void red_add_v4(float* p, float a, float b, float c, float d) {
    asm volatile("red.global.add.v4.f32 [%0], {%1, %2, %3, %4};"
                 :: "l"(p), "f"(a), "f"(b), "f"(c), "f"(d) : "memory");
}
__device__ __forceinline__ void red_max_s32(int* p, int v) {
    asm volatile("red.global.max.s32 [%0], %1;" :: "l"(p), "r"(v) : "memory");
}

// ---------------- k_init_seg ------------------------------------------------
__global__ void k_init_seg() {
    int i = blockIdx.x * 256 + threadIdx.x;
    if (i < NN * 4) { g_maxenc[i] = 0x80000000; g_sum[i] = 0.0f; }
    if (i < NN) g_cur[i] = 0;
}

// ---------------- k_hist ----------------------------------------------------
__global__ void k_hist(const int* __restrict__ dst) {
    int e = blockIdx.x * 256 + threadIdx.x;
    atomicAdd(&g_cur[dst[e]], 1);
}

// ---------------- k_nodeproj (unchanged) ------------------------------------
__global__ __launch_bounds__(512) void k_nodeproj(
    const float* __restrict__ nf, const float* __restrict__ Wsrc,
    const float* __restrict__ Wdst)
{
    extern __shared__ __align__(16) u64 sm[];
    u64* Wdup = sm;                  // 16384 u64
    u64* xs   = sm + 16384;          // 8192 u64
    int tid  = threadIdx.x;
    int warp = tid >> 5;
    int lane = tid & 31;
    int n0w  = blockIdx.x * 128 + warp * 8;

    for (int idx = tid; idx < 16384; idx += 512) {
        int k = idx >> 7, c = idx & 127;
        float w = (c < 64) ? Wsrc[c * 128 + k] : Wdst[(c - 64) * 128 + k];
        Wdup[idx] = pack2(w, w);
    }
    {
        int nl = lane >> 2, q = lane & 3;
        int nidx = min(n0w + nl, NN - 1);
        const float4* nfp = (const float4*)(nf + (size_t)nidx * 128 + q * 32);
        float* xf = (float*)(xs + warp * 512);
        int coff = ((nl >> 1) << 1) + (nl & 1);
        #pragma unroll
        for (int i = 0; i < 8; i++) {
            float4 v = nfp[i];
            int kb = q * 32 + 4 * i;
            xf[(kb + 0) * 8 + coff] = v.x;
            xf[(kb + 1) * 8 + coff] = v.y;
            xf[(kb + 2) * 8 + coff] = v.z;
            xf[(kb + 3) * 8 + coff] = v.w;
        }
    }
    __syncthreads();

    u64 acc[4][4];
    #pragma unroll
    for (int p = 0; p < 4; p++)
        #pragma unroll
        for (int c = 0; c < 4; c++) acc[p][c] = 0ull;

    const u64* xp = xs + warp * 512;
    #pragma unroll 4
    for (int k = 0; k < 128; k++) {
        ulonglong2 wa = *(const ulonglong2*)(Wdup + k * 128 + 4 * lane);
        ulonglong2 wb = *(const ulonglong2*)(Wdup + k * 128 + 4 * lane + 2);
        ulonglong2 x0 = *(const ulonglong2*)(xp + k * 4);
        ulonglong2 x1 = *(const ulonglong2*)(xp + k * 4 + 2);
        fma2(acc[0][0], x0.x, wa.x); fma2(acc[0][1], x0.x, wa.y);
        fma2(acc[0][2], x0.x, wb.x); fma2(acc[0][3], x0.x, wb.y);
        fma2(acc[1][0], x0.y, wa.x); fma2(acc[1][1], x0.y, wa.y);
        fma2(acc[1][2], x0.y, wb.x); fma2(acc[1][3], x0.y, wb.y);
        fma2(acc[2][0], x1.x, wa.x); fma2(acc[2][1], x1.x, wa.y);
        fma2(acc[2][2], x1.x, wb.x); fma2(acc[2][3], x1.x, wb.y);
        fma2(acc[3][0], x1.y, wa.x); fma2(acc[3][1], x1.y, wa.y);
        fma2(acc[3][2], x1.y, wb.x); fma2(acc[3][3], x1.y, wb.y);
    }

    float* outb = (lane < 16) ? g_fs : g_fd;
    int cc0 = (4 * lane) & 63;
    #pragma unroll
    for (int p = 0; p < 4; p++) {
        int nlo = n0w + 2 * p;
        if (nlo < NN) {
            float4 v = make_float4(lo32(acc[p][0]), lo32(acc[p][1]),
                                   lo32(acc[p][2]), lo32(acc[p][3]));
            *(float4*)(outb + (size_t)nlo * 64 + cc0) = v;
        }
        if (nlo + 1 < NN) {
            float4 v = make_float4(hi32(acc[p][0]), hi32(acc[p][1]),
                                   hi32(acc[p][2]), hi32(acc[p][3]));
            *(float4*)(outb + (size_t)(nlo + 1) * 64 + cc0) = v;
        }
    }
}

// ---------------- k_edge v4 -------------------------------------------------
// 256 thr = 8 warps, 24 edges/warp, 192 edges/block, 3 blocks/SM.
// Phase 1: GEMV, lane owns cols 2l,2l+1 of 12 edge-pairs (acc = 24 u64).
// Phase 2: acc -> smem eproj (pad-65 rows), thread = edge epilogue, no shfl.
__global__ __launch_bounds__(256, 3) void k_edge(
    const float* __restrict__ ef, const float* __restrict__ We,
    const float* __restrict__ attn,
    const int* __restrict__ src, const int* __restrict__ dst)
{
    extern __shared__ __align__(16) u64 esm[];
    u64*   Wdup  = esm;                 // [0,2048)   16 KB
    u64*   xs    = esm + 2048;          // [2048,5120) 24 KB (8 warps x 384)
    u64*   epj   = esm;                 // overlay [0,6240) 49.9 KB
    float* attns = (float*)(esm + 6240);// 256 B, beyond overlay

    int tid  = threadIdx.x;
    int warp = tid >> 5;
    int lane = tid & 31;
    int e0   = blockIdx.x * EPB;
    int e0w  = e0 + warp * EPW;

    for (int idx = tid; idx < 2048; idx += 256) {
        int k = idx >> 6, c = idx & 63;
        float w = We[c * 32 + k];
        Wdup[idx] = pack2(w, w);
    }
    if (tid < 64) attns[tid] = attn[tid];

    if (lane < EPW) {                       // stage 24 edges x 32 feats
        int e = min(e0w + lane, NE - 1);
        const float4* efp = (const float4*)(ef + (size_t)e * 32);
        float* xf = (float*)(xs + warp * 384);   // row stride 24 floats
        #pragma unroll
        for (int i = 0; i < 8; i++) {
            float4 v = efp[i];
            xf[(4 * i + 0) * 24 + lane] = v.x;
            xf[(4 * i + 1) * 24 + lane] = v.y;
            xf[(4 * i + 2) * 24 + lane] = v.z;
            xf[(4 * i + 3) * 24 + lane] = v.w;
        }
    }
    __syncthreads();

    u64 acc[12][2];
    #pragma unroll
    for (int p = 0; p < 12; p++) { acc[p][0] = 0ull; acc[p][1] = 0ull; }

    const u64* xp = xs + warp * 384;
    #pragma unroll 4
    for (int k = 0; k < 32; k++) {
        ulonglong2 wv = *(const ulonglong2*)(Wdup + k * 64 + 2 * lane);
        #pragma unroll
        for (int j = 0; j < 6; j++) {
            ulonglong2 xv = *(const ulonglong2*)(xp + k * 12 + 2 * j);
            fma2(acc[2 * j][0],     xv.x, wv.x);
            fma2(acc[2 * j][1],     xv.x, wv.y);
            fma2(acc[2 * j + 1][0], xv.y, wv.x);
            fma2(acc[2 * j + 1][1], xv.y, wv.y);
        }
    }
    __syncthreads();                         // xs/Wdup dead -> overlay

    #pragma unroll
    for (int p = 0; p < 12; p++) {           // eproj[pair][col] u64, pad 65
        u64* row = epj + (size_t)(warp * 12 + p) * 65;
        row[2 * lane]     = acc[p][0];
        row[2 * lane + 1] = acc[p][1];
    }
    __syncthreads();

    // ---- phase 2: thread = edge ----
    if (tid < EPB) {
        int e  = e0 + tid;
        bool valid = e < NE;
        int ec = min(e, NE - 1);
        int s = src[ec], d = dst[ec];
        // float view: value(col c) at eprow[2*c]; banks (e + 2c) % 32 -> clean
        const float* eprow = (const float*)(epj + (size_t)(tid >> 1) * 65) + (tid & 1);
        const float4* fsp = (const float4*)(g_fs + (size_t)s * 64);
        const float4* fdp = (const float4*)(g_fd + (size_t)d * 64);
        const float4* at4 = (const float4*)attns;
        float lg[4];
        #pragma unroll
        for (int h = 0; h < 4; h++) {
            float acch = 0.f;
            #pragma unroll
            for (int q = 0; q < 4; q++) {
                int c0 = h * 16 + q * 4;
                float4 a = fsp[h * 4 + q];
                float4 b = fdp[h * 4 + q];
                float t0 = eprow[2 * (c0 + 0)] + a.x + b.x;
                float t1 = eprow[2 * (c0 + 1)] + a.y + b.y;
                float t2 = eprow[2 * (c0 + 2)] + a.z + b.z;
                float t3 = eprow[2 * (c0 + 3)] + a.w + b.w;
                t0 = fmaxf(t0, 0.2f * t0);
                t1 = fmaxf(t1, 0.2f * t1);
                t2 = fmaxf(t2, 0.2f * t2);
                t3 = fmaxf(t3, 0.2f * t3);
                float4 at = at4[h * 4 + q];
                acch += t0 * at.x + t1 * at.y + t2 * at.z + t3 * at.w;
            }
            lg[h] = acch;
        }
        if (valid) {
            ((float4*)g_logit)[e] = make_float4(lg[0], lg[1], lg[2], lg[3]);
            #pragma unroll
            for (int h = 0; h < 4; h++)
                red_max_s32(&g_maxenc[d * 4 + h], fenc(lg[h]));
        }
    }
}

// ---------------- CSR scan kernels -----------------------------------------
__global__ void k_scan1() {
    __shared__ int red[256];
    int b = blockIdx.x, t = threadIdx.x;
    int s = 0;
    #pragma unroll
    for (int q = 0; q < 4; q++) {
        int idx = b * 1024 + q * 256 + t;
        if (idx < NN) s += g_cur[idx];
    }
    red[t] = s; __syncthreads();
    for (int o = 128; o > 0; o >>= 1) {
        if (t < o) red[t] += red[t + o];
        __syncthreads();
    }
    if (t == 0) g_part[b] = red[0];
}

__global__ void k_scan2() {
    if (threadIdx.x == 0) {
        int run = 0;
        for (int b = 0; b < NB_SCAN; b++) { g_partoff[b] = run; run += g_part[b]; }
        g_off[NN] = run;
    }
}

__global__ __launch_bounds__(1024) void k_scan3() {
    __shared__ int sbuf[1024];
    int b = blockIdx.x, t = threadIdx.x;
    int i = b * 1024 + t;
    int v = (i < NN) ? g_cur[i] : 0;
    sbuf[t] = v; __syncthreads();
    #pragma unroll
    for (int o = 1; o < 1024; o <<= 1) {
        int x = (t >= o) ? sbuf[t - o] : 0;
        __syncthreads();
        sbuf[t] += x;
        __syncthreads();
    }
    if (i < NN) {
        int excl = g_partoff[b] + sbuf[t] - v;
        g_off[i] = excl;
        g_cur[i] = excl;
    }
}

__global__ void k_scatter(const int* __restrict__ dst) {
    int e = blockIdx.x * 256 + threadIdx.x;
    int pos = atomicAdd(&g_cur[dst[e]], 1);
    g_eid[pos] = e;
}

// ---------------- k_soft ----------------------------------------------------
__global__ __launch_bounds__(256) void k_soft(const int* __restrict__ dst) {
    int e = blockIdx.x * 256 + threadIdx.x;
    int d = dst[e];
    float4 l = ((const float4*)g_logit)[e];
    int4 m = *(const int4*)(g_maxenc + d * 4);
    float4 ex;
    ex.x = __expf(l.x - fdec(m.x));
    ex.y = __expf(l.y - fdec(m.y));
    ex.z = __expf(l.z - fdec(m.z));
    ex.w = __expf(l.w - fdec(m.w));
    ((float4*)g_logit)[e] = ex;
    red_add_v4(g_sum + d * 4, ex.x, ex.y, ex.z, ex.w);
}

// ---------------- k_pull (CSR aggregation + alpha write) --------------------
__global__ __launch_bounds__(256) void k_pull(
    const int* __restrict__ src, const float* __restrict__ bias,
    float* __restrict__ rst, float* __restrict__ alpha_out)
{
    int d = blockIdx.x * 8 + (threadIdx.x >> 5);     // NN divisible by 8
    int L = threadIdx.x & 31;
    int h = L >> 3;
    int row0 = g_off[d], row1 = g_off[d + 1];
    float invs = __fdividef(1.0f, g_sum[d * 4 + h]);
    bool wr = (L & 7) == 0;                          // lanes 0,8,16,24 write alpha

    u64 acc = 0ull;
    for (int base = row0; base < row1; base += 32) {
        int n = min(32, row1 - base);
        int eidL = (base + L < row1) ? g_eid[base + L] : 0;
        int sL   = src[eidL];
        int i = 0;
        for (; i + 2 <= n; i += 2) {
            int e0 = __shfl_sync(0xffffffffu, eidL, i);
            int e1 = __shfl_sync(0xffffffffu, eidL, i + 1);
            int s0 = __shfl_sync(0xffffffffu, sL, i);
            int s1 = __shfl_sync(0xffffffffu, sL, i + 1);
            float al0 = g_logit[(size_t)e0 * 4 + h] * invs;
            float al1 = g_logit[(size_t)e1 * 4 + h] * invs;
            if (wr) {
                alpha_out[(size_t)e0 * 4 + h] = al0;
                alpha_out[(size_t)e1 * 4 + h] = al1;
            }
            float2 f0 = *(const float2*)(g_fs + (size_t)s0 * 64 + 2 * L);
            float2 f1 = *(const float2*)(g_fs + (size_t)s1 * 64 + 2 * L);
            fma2(acc, pack2(al0, al0), pack2(f0.x, f0.y));
            fma2(acc, pack2(al1, al1), pack2(f1.x, f1.y));
        }
        if (i < n) {
            int e0 = __shfl_sync(0xffffffffu, eidL, i);
            int s0 = __shfl_sync(0xffffffffu, sL, i);
            float al0 = g_logit[(size_t)e0 * 4 + h] * invs;
            if (wr) alpha_out[(size_t)e0 * 4 + h] = al0;
            float2 f0 = *(const float2*)(g_fs + (size_t)s0 * 64 + 2 * L);
            fma2(acc, pack2(al0, al0), pack2(f0.x, f0.y));
        }
    }
    float2 b2 = *(const float2*)(bias + 2 * L);
    float2 o = make_float2(lo32(acc) + b2.x, hi32(acc) + b2.y);
    *(float2*)(rst + (size_t)d * 64 + 2 * L) = o;
}

// ---------------- launch ----------------------------------------------------
extern "C" void kernel_launch(void* const* d_in, const int* in_sizes, int n_in,
                              void* d_out, int out_size) {
    const float* node_feat = (const float*)d_in[0];
    const float* edge_feat = (const float*)d_in[1];
    const float* W_src     = (const float*)d_in[2];
    const float* W_dst     = (const float*)d_in[3];
    const float* W_edge    = (const float*)d_in[4];
    const float* attn      = (const float*)d_in[5];
    const float* bias      = (const float*)d_in[6];
    const int*   src       = (const int*)d_in[7];
    const int*   dst       = (const int*)d_in[8];
    float* rst   = (float*)d_out;                       // [N,64]
    float* alpha = (float*)d_out + (size_t)NN * OUTD;   // [E,4]

    const int NODE_SMEM = (16384 + 8192) * 8;           // 196608 B
    const int EDGE_SMEM = 6240 * 8 + 256;               // 50176 B
    cudaFuncSetAttribute(k_nodeproj, cudaFuncAttributeMaxDynamicSharedMemorySize,
                         NODE_SMEM);
    cudaFuncSetAttribute(k_edge, cudaFuncAttributeMaxDynamicSharedMemorySize,
                         EDGE_SMEM);

    k_init_seg<<<(NN * 4 + 255) / 256, 256>>>();                        // 0
    k_hist<<<NE / 256, 256>>>(dst);                                     // 1
    k_nodeproj<<<(NN + 127) / 128, 512, NODE_SMEM>>>(node_feat, W_src, W_dst); // 2
    k_edge<<<NBLK_E, 256, EDGE_SMEM>>>(edge_feat, W_edge, attn, src, dst);     // 3
    k_scan1<<<NB_SCAN, 256>>>();                                        // 4
    k_scan2<<<1, 32>>>();                                               // 5
    k_scan3<<<NB_SCAN, 1024>>>();                                       // 6
    k_scatter<<<NE / 256, 256>>>(dst);                                  // 7
    k_soft<<<NE / 256, 256>>>(dst);                                     // 8
    k_pull<<<NN / 8, 256>>>(src, bias, rst, alpha);                     // 9
}

// round 12
// speedup vs baseline: 1.0705x; 1.0705x over previous
#include <cuda_runtime.h>
#include <cstdint>

// ---------------------------------------------------------------------------
// EdgeGATv2: N=100000 nodes, E=1600000 edges, IN=128, OUT=64 (H=4 x HD=16),
// EDGE_DIM=32.  Output = [rst (N*64 floats) ; alpha (E*4 floats)].
//
// R10: R9 design with the alignment bug fixed (epj row stride 65 -> 66 u64,
// 16B-aligned rows; phase-1 spill via single STS.128, conflict-free).
// ---------------------------------------------------------------------------

#define NN    100000
#define NE    1600000
#define OUTD  64
#define NB_SCAN 98          // ceil(NN/1024)

#define EPB   192           // edges per block (k_edge)
#define EPW   24            // edges per warp
#define NBLK_E ((NE + EPB - 1) / EPB)   // 8334
#define EPJ_STRIDE 66       // u64 per epj row (even -> 16B aligned)

typedef unsigned long long u64;

// ---------------- scratch (no allocations allowed) -------------------------
__device__ float g_fs[(size_t)NN * OUTD];     // 25.6 MB
__device__ float g_fd[(size_t)NN * OUTD];     // 25.6 MB
__device__ float g_logit[(size_t)NE * 4];     // 25.6 MB (reused as ex)
__device__ int   g_maxenc[NN * 4];            // 1.6 MB
__device__ float g_sum[NN * 4];               // 1.6 MB
__device__ int   g_off[NN + 1];               // CSR row offsets
__device__ int   g_cur[NN];                   // degree, then scatter cursor
__device__ int   g_eid[NE];                   // CSR edge ids
__device__ int   g_part[NB_SCAN];             // scan partials
__device__ int   g_partoff[NB_SCAN];

// ---------------- helpers ---------------------------------------------------
__device__ __forceinline__ u64 pack2(float lo, float hi) {
    u64 r; asm("mov.b64 %0, {%1, %2};" : "=l"(r) : "f"(lo), "f"(hi)); return r;
}
__device__ __forceinline__ void fma2(u64& d, u64 a, u64 b) {
    asm("fma.rn.f32x2 %0, %1, %2, %0;" : "+l"(d) : "l"(a), "l"(b));
}
__device__ __forceinline__ float lo32(u64 v) { return __uint_as_float((unsigned)v); }
__device__ __forceinline__ float hi32(u64 v) { return __uint_as_float((unsigned)(v >> 32)); }

__device__ __forceinline__ int fenc(float f) {
    int i = __float_as_int(f);
    return i >= 0 ? i : (i ^ 0x7fffffff);
}
__device__ __forceinline__ float fdec(int e) {
    return __int_as_float(e >= 0 ? e : (e ^ 0x7fffffff));
}

__device__ __forceinline__ void red_add_v4(float* p, float a, float b, float c, float d) {
    asm volatile("red.global.add.v4.f32 [%0], {%1, %2, %3, %4};"
                 :: "l"(p), "f"(a), "f"(b), "f"(c), "f"(d) : "memory");
}
__device__ __forceinline__ void red_max_s32(int* p, int v) {
    asm volatile("red.global.max.s32 [%0], %1;" :: "l"(p), "r"(v) : "memory");
}

// ---------------- k_init_seg ------------------------------------------------
__global__ void k_init_seg() {
    int i = blockIdx.x * 256 + threadIdx.x;
    if (i < NN * 4) { g_maxenc[i] = 0x80000000; g_sum[i] = 0.0f; }
    if (i < NN) g_cur[i] = 0;
}

// ---------------- k_hist ----------------------------------------------------
__global__ void k_hist(const int* __restrict__ dst) {
    int e = blockIdx.x * 256 + threadIdx.x;
    atomicAdd(&g_cur[dst[e]], 1);
}

// ---------------- k_nodeproj (unchanged) ------------------------------------
__global__ __launch_bounds__(512) void k_nodeproj(
    const float* __restrict__ nf, const float* __restrict__ Wsrc,
    const float* __restrict__ Wdst)
{
    extern __shared__ __align__(16) u64 sm[];
    u64* Wdup = sm;                  // 16384 u64
    u64* xs   = sm + 16384;          // 8192 u64
    int tid  = threadIdx.x;
    int warp = tid >> 5;
    int lane = tid & 31;
    int n0w  = blockIdx.x * 128 + warp * 8;

    for (int idx = tid; idx < 16384; idx += 512) {
        int k = idx >> 7, c = idx & 127;
        float w = (c < 64) ? Wsrc[c * 128 + k] : Wdst[(c - 64) * 128 + k];
        Wdup[idx] = pack2(w, w);
    }
    {
        int nl = lane >> 2, q = lane & 3;
        int nidx = min(n0w + nl, NN - 1);
        const float4* nfp = (const float4*)(nf + (size_t)nidx * 128 + q * 32);
        float* xf = (float*)(xs + warp * 512);
        int coff = ((nl >> 1) << 1) + (nl & 1);
        #pragma unroll
        for (int i = 0; i < 8; i++) {
            float4 v = nfp[i];
            int kb = q * 32 + 4 * i;
            xf[(kb + 0) * 8 + coff] = v.x;
            xf[(kb + 1) * 8 + coff] = v.y;
            xf[(kb + 2) * 8 + coff] = v.z;
            xf[(kb + 3) * 8 + coff] = v.w;
        }
    }
    __syncthreads();

    u64 acc[4][4];
    #pragma unroll
    for (int p = 0; p < 4; p++)
        #pragma unroll
        for (int c = 0; c < 4; c++) acc[p][c] = 0ull;

    const u64* xp = xs + warp * 512;
    #pragma unroll 4
    for (int k = 0; k < 128; k++) {
        ulonglong2 wa = *(const ulonglong2*)(Wdup + k * 128 + 4 * lane);
        ulonglong2 wb = *(const ulonglong2*)(Wdup + k * 128 + 4 * lane + 2);
        ulonglong2 x0 = *(const ulonglong2*)(xp + k * 4);
        ulonglong2 x1 = *(const ulonglong2*)(xp + k * 4 + 2);
        fma2(acc[0][0], x0.x, wa.x); fma2(acc[0][1], x0.x, wa.y);
        fma2(acc[0][2], x0.x, wb.x); fma2(acc[0][3], x0.x, wb.y);
        fma2(acc[1][0], x0.y, wa.x); fma2(acc[1][1], x0.y, wa.y);
        fma2(acc[1][2], x0.y, wb.x); fma2(acc[1][3], x0.y, wb.y);
        fma2(acc[2][0], x1.x, wa.x); fma2(acc[2][1], x1.x, wa.y);
        fma2(acc[2][2], x1.x, wb.x); fma2(acc[2][3], x1.x, wb.y);
        fma2(acc[3][0], x1.y, wa.x); fma2(acc[3][1], x1.y, wa.y);
        fma2(acc[3][2], x1.y, wb.x); fma2(acc[3][3], x1.y, wb.y);
    }

    float* outb = (lane < 16) ? g_fs : g_fd;
    int cc0 = (4 * lane) & 63;
    #pragma unroll
    for (int p = 0; p < 4; p++) {
        int nlo = n0w + 2 * p;
        if (nlo < NN) {
            float4 v = make_float4(lo32(acc[p][0]), lo32(acc[p][1]),
                                   lo32(acc[p][2]), lo32(acc[p][3]));
            *(float4*)(outb + (size_t)nlo * 64 + cc0) = v;
        }
        if (nlo + 1 < NN) {
            float4 v = make_float4(hi32(acc[p][0]), hi32(acc[p][1]),
                                   hi32(acc[p][2]), hi32(acc[p][3]));
            *(float4*)(outb + (size_t)(nlo + 1) * 64 + cc0) = v;
        }
    }
}

// ---------------- k_edge v6 -------------------------------------------------
// 256 thr = 8 warps, 24 edges/warp, 192 edges/block, 3 blocks/SM.
// Phase 1: GEMV, lane owns cols 2l,2l+1; acc[p] packs edges (2p,2p+1).
// Phase 2: acc -> smem epj (stride-66 rows, 16B aligned, conflict-free
// STS/LDS.128), then warp-cooperative per-edge epilogue.
__global__ __launch_bounds__(256, 3) void k_edge(
    const float* __restrict__ ef, const float* __restrict__ We,
    const float* __restrict__ attn,
    const int* __restrict__ src, const int* __restrict__ dst)
{
    extern __shared__ __align__(16) u64 esm[];
    u64*   Wdup  = esm;                 // [0,2048)   16 KB
    u64*   xs    = esm + 2048;          // [2048,5120) 24 KB (8 warps x 384)
    u64*   epj   = esm;                 // overlay [0, 96*66) = 6336 u64
    float* attns = (float*)(esm + 6336);// 256 B, beyond overlay

    int tid  = threadIdx.x;
    int warp = tid >> 5;
    int lane = tid & 31;
    int e0   = blockIdx.x * EPB;
    int e0w  = e0 + warp * EPW;

    for (int idx = tid; idx < 2048; idx += 256) {
        int k = idx >> 6, c = idx & 63;
        float w = We[c * 32 + k];
        Wdup[idx] = pack2(w, w);
    }
    if (tid < 64) attns[tid] = attn[tid];

    if (lane < EPW) {                       // stage 24 edges x 32 feats
        int e = min(e0w + lane, NE - 1);
        const float4* efp = (const float4*)(ef + (size_t)e * 32);
        float* xf = (float*)(xs + warp * 384);   // row stride 24 floats
        #pragma unroll
        for (int i = 0; i < 8; i++) {
            float4 v = efp[i];
            xf[(4 * i + 0) * 24 + lane] = v.x;
            xf[(4 * i + 1) * 24 + lane] = v.y;
            xf[(4 * i + 2) * 24 + lane] = v.z;
            xf[(4 * i + 3) * 24 + lane] = v.w;
        }
    }
    __syncthreads();

    u64 acc[12][2];
    #pragma unroll
    for (int p = 0; p < 12; p++) { acc[p][0] = 0ull; acc[p][1] = 0ull; }

    const u64* xp = xs + warp * 384;
    #pragma unroll 4
    for (int k = 0; k < 32; k++) {
        ulonglong2 wv = *(const ulonglong2*)(Wdup + k * 64 + 2 * lane);
        #pragma unroll
        for (int j = 0; j < 6; j++) {
            ulonglong2 xv = *(const ulonglong2*)(xp + k * 12 + 2 * j);
            fma2(acc[2 * j][0],     xv.x, wv.x);
            fma2(acc[2 * j][1],     xv.x, wv.y);
            fma2(acc[2 * j + 1][0], xv.y, wv.x);
            fma2(acc[2 * j + 1][1], xv.y, wv.y);
        }
    }
    __syncthreads();                         // xs/Wdup dead -> overlay

    // epj row r = warp*12 + p: u64 index c = col c of edges (2p, 2p+1)
    #pragma unroll
    for (int p = 0; p < 12; p++) {
        u64* row = epj + (size_t)(warp * 12 + p) * EPJ_STRIDE;
        ulonglong2 v; v.x = acc[p][0]; v.y = acc[p][1];
        *(ulonglong2*)(row + 2 * lane) = v;          // 16B aligned, bank-clean
    }
    __syncthreads();

    // ---- phase 2: warp-cooperative epilogue over this warp's 24 edges ----
    float a0 = attns[2 * lane], a1 = attns[2 * lane + 1];
    int hsel = lane >> 3;
    #pragma unroll 4
    for (int ew = 0; ew < EPW; ew++) {
        int e = e0w + ew;
        if (e >= NE) break;                  // lane-uniform
        int s = src[e], d = dst[e];          // uniform-address LDG
        const u64* row = epj + (size_t)(warp * 12 + (ew >> 1)) * EPJ_STRIDE;
        ulonglong2 pv = *(const ulonglong2*)(row + 2 * lane);  // cols 2L,2L+1
        float v0, v1;
        if (ew & 1) { v0 = hi32(pv.x); v1 = hi32(pv.y); }
        else        { v0 = lo32(pv.x); v1 = lo32(pv.y); }
        float2 fs2 = *(const float2*)(g_fs + (size_t)s * 64 + 2 * lane);
        float2 fd2 = *(const float2*)(g_fd + (size_t)d * 64 + 2 * lane);
        float t0 = v0 + fs2.x + fd2.x;
        float t1 = v1 + fs2.y + fd2.y;
        t0 = fmaxf(t0, 0.2f * t0);
        t1 = fmaxf(t1, 0.2f * t1);
        float pr = t0 * a0 + t1 * a1;
        pr += __shfl_xor_sync(0xffffffffu, pr, 1);
        pr += __shfl_xor_sync(0xffffffffu, pr, 2);
        pr += __shfl_xor_sync(0xffffffffu, pr, 4);
        if ((lane & 7) == 0) {
            g_logit[(size_t)e * 4 + hsel] = pr;
            red_max_s32(&g_maxenc[d * 4 + hsel], fenc(pr));
        }
    }
}

// ---------------- CSR scan kernels -----------------------------------------
__global__ void k_scan1() {
    __shared__ int red[256];
    int b = blockIdx.x, t = threadIdx.x;
    int s = 0;
    #pragma unroll
    for (int q = 0; q < 4; q++) {
        int idx = b * 1024 + q * 256 + t;
        if (idx < NN) s += g_cur[idx];
    }
    red[t] = s; __syncthreads();
    for (int o = 128; o > 0; o >>= 1) {
        if (t < o) red[t] += red[t + o];
        __syncthreads();
    }
    if (t == 0) g_part[b] = red[0];
}

__global__ void k_scan2() {
    if (threadIdx.x == 0) {
        int run = 0;
        for (int b = 0; b < NB_SCAN; b++) { g_partoff[b] = run; run += g_part[b]; }
        g_off[NN] = run;
    }
}

__global__ __launch_bounds__(1024) void k_scan3() {
    __shared__ int sbuf[1024];
    int b = blockIdx.x, t = threadIdx.x;
    int i = b * 1024 + t;
    int v = (i < NN) ? g_cur[i] : 0;
    sbuf[t] = v; __syncthreads();
    #pragma unroll
    for (int o = 1; o < 1024; o <<= 1) {
        int x = (t >= o) ? sbuf[t - o] : 0;
        __syncthreads();
        sbuf[t] += x;
        __syncthreads();
    }
    if (i < NN) {
        int excl = g_partoff[b] + sbuf[t] - v;
        g_off[i] = excl;
        g_cur[i] = excl;
    }
}

__global__ void k_scatter(const int* __restrict__ dst) {
    int e = blockIdx.x * 256 + threadIdx.x;
    int pos = atomicAdd(&g_cur[dst[e]], 1);
    g_eid[pos] = e;
}

// ---------------- k_soft ----------------------------------------------------
__global__ __launch_bounds__(256) void k_soft(const int* __restrict__ dst) {
    int e = blockIdx.x * 256 + threadIdx.x;
    int d = dst[e];
    float4 l = ((const float4*)g_logit)[e];
    int4 m = *(const int4*)(g_maxenc + d * 4);
    float4 ex;
    ex.x = __expf(l.x - fdec(m.x));
    ex.y = __expf(l.y - fdec(m.y));
    ex.z = __expf(l.z - fdec(m.z));
    ex.w = __expf(l.w - fdec(m.w));
    ((float4*)g_logit)[e] = ex;
    red_add_v4(g_sum + d * 4, ex.x, ex.y, ex.z, ex.w);
}

// ---------------- k_pull (CSR aggregation + alpha write) --------------------
__global__ __launch_bounds__(256) void k_pull(
    const int* __restrict__ src, const float* __restrict__ bias,
    float* __restrict__ rst, float* __restrict__ alpha_out)
{
    int d = blockIdx.x * 8 + (threadIdx.x >> 5);     // NN divisible by 8
    int L = threadIdx.x & 31;
    int h = L >> 3;
    int row0 = g_off[d], row1 = g_off[d + 1];
    float invs = __fdividef(1.0f, g_sum[d * 4 + h]);
    bool wr = (L & 7) == 0;                          // lanes 0,8,16,24 write alpha

    u64 acc = 0ull;
    for (int base = row0; base < row1; base += 32) {
        int n = min(32, row1 - base);
        int eidL = (base + L < row1) ? g_eid[base + L] : 0;
        int sL   = src[eidL];
        int i = 0;
        for (; i + 2 <= n; i += 2) {
            int e0 = __shfl_sync(0xffffffffu, eidL, i);
            int e1 = __shfl_sync(0xffffffffu, eidL, i + 1);
            int s0 = __shfl_sync(0xffffffffu, sL, i);
            int s1 = __shfl_sync(0xffffffffu, sL, i + 1);
            float al0 = g_logit[(size_t)e0 * 4 + h] * invs;
            float al1 = g_logit[(size_t)e1 * 4 + h] * invs;
            if (wr) {
                alpha_out[(size_t)e0 * 4 + h] = al0;
                alpha_out[(size_t)e1 * 4 + h] = al1;
            }
            float2 f0 = *(const float2*)(g_fs + (size_t)s0 * 64 + 2 * L);
            float2 f1 = *(const float2*)(g_fs + (size_t)s1 * 64 + 2 * L);
            fma2(acc, pack2(al0, al0), pack2(f0.x, f0.y));
            fma2(acc, pack2(al1, al1), pack2(f1.x, f1.y));
        }
        if (i < n) {
            int e0 = __shfl_sync(0xffffffffu, eidL, i);
            int s0 = __shfl_sync(0xffffffffu, sL, i);
            float al0 = g_logit[(size_t)e0 * 4 + h] * invs;
            if (wr) alpha_out[(size_t)e0 * 4 + h] = al0;
            float2 f0 = *(const float2*)(g_fs + (size_t)s0 * 64 + 2 * L);
            fma2(acc, pack2(al0, al0), pack2(f0.x, f0.y));
        }
    }
    float2 b2 = *(const float2*)(bias + 2 * L);
    float2 o = make_float2(lo32(acc) + b2.x, hi32(acc) + b2.y);
    *(float2*)(rst + (size_t)d * 64 + 2 * L) = o;
}

// ---------------- launch ----------------------------------------------------
extern "C" void kernel_launch(void* const* d_in, const int* in_sizes, int n_in,
                              void* d_out, int out_size) {
    const float* node_feat = (const float*)d_in[0];
    const float* edge_feat = (const float*)d_in[1];
    const float* W_src     = (const float*)d_in[2];
    const float* W_dst     = (const float*)d_in[3];
    const float* W_edge    = (const float*)d_in[4];
    const float* attn      = (const float*)d_in[5];
    const float* bias      = (const float*)d_in[6];
    const int*   src       = (const int*)d_in[7];
    const int*   dst       = (const int*)d_in[8];
    float* rst   = (float*)d_out;                       // [N,64]
    float* alpha = (float*)d_out + (size_t)NN * OUTD;   // [E,4]

    const int NODE_SMEM = (16384 + 8192) * 8;           // 196608 B
    const int EDGE_SMEM = 6336 * 8 + 256;               // 50944 B
    cudaFuncSetAttribute(k_nodeproj, cudaFuncAttributeMaxDynamicSharedMemorySize,
                         NODE_SMEM);
    cudaFuncSetAttribute(k_edge, cudaFuncAttributeMaxDynamicSharedMemorySize,
                         EDGE_SMEM);

    k_init_seg<<<(NN * 4 + 255) / 256, 256>>>();                        // 0
    k_hist<<<NE / 256, 256>>>(dst);                                     // 1
    k_nodeproj<<<(NN + 127) / 128, 512, NODE_SMEM>>>(node_feat, W_src, W_dst); // 2
    k_edge<<<NBLK_E, 256, EDGE_SMEM>>>(edge_feat, W_edge, attn, src, dst);     // 3
    k_scan1<<<NB_SCAN, 256>>>();                                        // 4
    k_scan2<<<1, 32>>>();                                               // 5
    k_scan3<<<NB_SCAN, 1024>>>();                                       // 6
    k_scatter<<<NE / 256, 256>>>(dst);                                  // 7
    k_soft<<<NE / 256, 256>>>(dst);                                     // 8
    k_pull<<<NN / 8, 256>>>(src, bias, rst, alpha);                     // 9
}